// round 15
// baseline (speedup 1.0000x reference)
#include <cuda_runtime.h>
#include <cuda_fp16.h>
#include <cstdint>
#include <math.h>

// Problem constants
#define L      2048
#define DIM    4096
#define NH     32
#define NKV    8
#define HD     128
#define QDIM   (NH*HD)    // 4096
#define KVDIM  (NKV*HD)   // 1024
#define NTOT   (QDIM + 2*KVDIM)   // 6144 fused projection width
#define ATT_SCALE 0.08838834764831845f  // 128^-0.5

// ---------------------------------------------------------------------------
// Scratch (__device__ globals; no allocations allowed)
// ---------------------------------------------------------------------------
__device__ __half g_qh[L*QDIM];               // q fp16, roped, *ATT_SCALE
__device__ __half g_kh[L*KVDIM];              // k fp16, roped
__device__ __half g_vh[L*KVDIM];              // v fp16
__device__ float  g_cos[L*HD];                // rope cos table [t][j]
__device__ float  g_sin[L*HD];                // rope sin table [t][j]

// fp16 limbs (activations: hi+lo; weights: single limb, transposed)
__device__ __half g_xh[L*DIM],  g_xl[L*DIM];
__device__ __half g_ah[L*QDIM], g_al[L*QDIM];   // attention output hi/lo
__device__ __half g_wT[NTOT*DIM];        // (wq|wk|wv)^T [N=6144][K=4096]
__device__ __half g_woT[QDIM*DIM];       // wo^T  [N=4096][K=4096]

// ---------------------------------------------------------------------------
// PTX helpers (sm_80-era; valid on base compute_103 target)
// ---------------------------------------------------------------------------
__device__ __forceinline__ uint32_t smem_u32(const void* p) {
    uint32_t a;
    asm("{ .reg .u64 t; cvta.to.shared.u64 t, %1; cvt.u32.u64 %0, t; }" : "=r"(a) : "l"(p));
    return a;
}
__device__ __forceinline__ void cp16(void* smem, const void* g) {
    uint32_t s = smem_u32(smem);
    asm volatile("cp.async.cg.shared.global [%0], [%1], 16;" :: "r"(s), "l"(g));
}
#define CP_COMMIT() asm volatile("cp.async.commit_group;")
#define CP_WAIT0()  asm volatile("cp.async.wait_group 0;")

__device__ __forceinline__ void ldsm4(uint32_t* r, uint32_t addr) {
    asm volatile("ldmatrix.sync.aligned.m8n8.x4.shared.b16 {%0,%1,%2,%3}, [%4];"
                 : "=r"(r[0]), "=r"(r[1]), "=r"(r[2]), "=r"(r[3]) : "r"(addr));
}
__device__ __forceinline__ void ldsm4t(uint32_t* r, uint32_t addr) {
    asm volatile("ldmatrix.sync.aligned.m8n8.x4.trans.shared.b16 {%0,%1,%2,%3}, [%4];"
                 : "=r"(r[0]), "=r"(r[1]), "=r"(r[2]), "=r"(r[3]) : "r"(addr));
}
__device__ __forceinline__ void mma_f16(float* c, const uint32_t* a, const uint32_t* b) {
    asm volatile("mma.sync.aligned.m16n8k16.row.col.f32.f16.f16.f32 "
                 "{%0,%1,%2,%3},{%4,%5,%6,%7},{%8,%9},{%0,%1,%2,%3};"
                 : "+f"(c[0]), "+f"(c[1]), "+f"(c[2]), "+f"(c[3])
                 : "r"(a[0]), "r"(a[1]), "r"(a[2]), "r"(a[3]), "r"(b[0]), "r"(b[1]));
}
__device__ __forceinline__ uint32_t pack_h2(float lo, float hi) {
    uint32_t r;
    asm("cvt.rn.f16x2.f32 %0, %1, %2;" : "=r"(r) : "f"(hi), "f"(lo));
    return r;
}

// ---------------------------------------------------------------------------
// Rope cos/sin table
// ---------------------------------------------------------------------------
__global__ void rope_tab_kernel(float* __restrict__ ct, float* __restrict__ st)
{
    int idx = blockIdx.x * blockDim.x + threadIdx.x;   // t*128 + j
    if (idx >= L * HD) return;
    int t = idx >> 7, j = idx & 127;
    const float Cc = 0.14391156644565413f; // ln(10000)/64
    float a = (float)t * expf(-Cc * (float)(j & 63));
    float c, s;
    sincosf(a, &s, &c);
    ct[idx] = c;
    st[idx] = s;
}

// ---------------------------------------------------------------------------
// fp32 -> fp16 hi + fp16 lo split (x input)
// ---------------------------------------------------------------------------
__global__ void split_h(const float* __restrict__ x,
                        __half* __restrict__ h, __half* __restrict__ l, long n)
{
    long i = ((long)blockIdx.x * blockDim.x + threadIdx.x) * 4;
    if (i >= n) return;
    float4 v = *(const float4*)(x + i);
    float vv[4] = {v.x, v.y, v.z, v.w};
    __half hh[4], ll[4];
    #pragma unroll
    for (int j = 0; j < 4; j++) {
        hh[j] = __float2half_rn(vv[j]);
        ll[j] = __float2half_rn(vv[j] - __half2float(hh[j]));
    }
    *(__half2*)(h + i)     = __halves2half2(hh[0], hh[1]);
    *(__half2*)(h + i + 2) = __halves2half2(hh[2], hh[3]);
    *(__half2*)(l + i)     = __halves2half2(ll[0], ll[1]);
    *(__half2*)(l + i + 2) = __halves2half2(ll[2], ll[3]);
}

// ---------------------------------------------------------------------------
// Merged transpose+convert for all 4 weights.
// ---------------------------------------------------------------------------
__global__ void transT_all(const float* __restrict__ wq, const float* __restrict__ wk,
                           const float* __restrict__ wv, const float* __restrict__ wo,
                           __half* __restrict__ WT, __half* __restrict__ WOT)
{
    __shared__ float t[32][33];
    int bx = blockIdx.x;
    const float* W; __half* H; int N; int n0;
    if (bx < 128)       { W = wq; H = WT;                              N = QDIM;  n0 = bx * 32; }
    else if (bx < 160)  { W = wk; H = WT + (size_t)QDIM * DIM;         N = KVDIM; n0 = (bx - 128) * 32; }
    else if (bx < 192)  { W = wv; H = WT + (size_t)(QDIM + KVDIM) * DIM; N = KVDIM; n0 = (bx - 160) * 32; }
    else                { W = wo; H = WOT;                             N = DIM;   n0 = (bx - 192) * 32; }
    int k0 = blockIdx.y * 32;
    int tx = threadIdx.x, ty = threadIdx.y;
    #pragma unroll
    for (int r = ty; r < 32; r += 8)
        t[r][tx] = W[(size_t)(k0 + r) * N + n0 + tx];
    __syncthreads();
    #pragma unroll
    for (int r = ty; r < 32; r += 8)
        H[(size_t)(n0 + r) * 4096 + k0 + tx] = __float2half_rn(t[tx][r]);
}

// ---------------------------------------------------------------------------
// fp16 2x1-limb GEMM (R13-proven config): C[M,N] = (Ah+Al)[M,K] @ B^T[N,K].
// Block 128x128, BK=64, 256 threads, 8 warps (2M x 4N), warp tile 64x32.
// 2-stage cp.async pipeline, 2 CTAs/SM.
// MODE 0: plain fp32 C.  MODE 3: fused qkv epilogue.
// ---------------------------------------------------------------------------
#define GST    72                 // halves per smem row
#define LIMBB  18432              // bytes per array per stage (128*144)
#define STGB   (3*LIMBB)          // 55296 per stage
#define GEMM_SMEM (2*STGB)        // 110592 -> two CTAs fit

template<int MODE>
__global__ void __launch_bounds__(256, 2) gemm_h2(
    const __half* __restrict__ Ah, const __half* __restrict__ Al,
    const __half* __restrict__ B,
    float* __restrict__ C,
    __half* __restrict__ QH, __half* __restrict__ KH, __half* __restrict__ VH,
    const float* __restrict__ ctab, const float* __restrict__ stab,
    float* __restrict__ outk, float* __restrict__ outv, int has_out,
    int M, int N, int K)
{
    extern __shared__ char dyn_smem[];
    const uint32_t sb = smem_u32(dyn_smem);
    const int tid = threadIdx.x, lane = tid & 31, wid = tid >> 5;
    const int wm = (wid & 1) * 64, wn = (wid >> 1) * 32;
    const int lrow = lane & 15, lcol = (lane >> 4) * 8;
    const int m0 = blockIdx.y * 128, n0 = blockIdx.x * 128;

    const __half* gAh = Ah + (size_t)m0 * K;
    const __half* gAl = Al + (size_t)m0 * K;
    const __half* gB  = B  + (size_t)n0 * K;

    float acc[4][4][4] = {};
    const int nit = K / 64;

    auto load_stage = [&](int it) {
        const int s = it & 1;
        const int k0 = it * 64;
        char* base = dyn_smem + s * STGB;
        for (int i = tid; i < 1024; i += 256) {
            int row = i >> 3, c = i & 7;
            uint32_t so = (uint32_t)(row * 144 + c * 16);
            size_t go = (size_t)row * K + k0 + c * 8;
            cp16(base + so, gAh + go);
            cp16(base + LIMBB + so, gAl + go);
            cp16(base + 2 * LIMBB + so, gB + go);
        }
        CP_COMMIT();
    };

    load_stage(0);

    for (int it = 0; it < nit; it++) {
        const int s = it & 1;
        CP_WAIT0();
        __syncthreads();
        if (it + 1 < nit) load_stage(it + 1);

        const uint32_t aHb = sb + (uint32_t)(s * STGB);
        const uint32_t aLb = aHb + LIMBB;
        const uint32_t bb  = aHb + 2 * LIMBB;

        #pragma unroll
        for (int ks = 0; ks < 4; ks++) {
            uint32_t ah[4][4], al[4][4], bf[4][2];
            #pragma unroll
            for (int mi = 0; mi < 4; mi++) {
                uint32_t off = (uint32_t)((wm + mi * 16 + lrow) * GST + ks * 16 + lcol) * 2;
                ldsm4(ah[mi], aHb + off);
                ldsm4(al[mi], aLb + off);
            }
            #pragma unroll
            for (int nh = 0; nh < 2; nh++) {
                uint32_t off = (uint32_t)((wn + nh * 16 + lrow) * GST + ks * 16 + lcol) * 2;
                uint32_t r[4];
                ldsm4(r, bb + off);
                bf[nh*2][0] = r[0]; bf[nh*2][1] = r[2];
                bf[nh*2+1][0] = r[1]; bf[nh*2+1][1] = r[3];
            }
            #pragma unroll
            for (int mi = 0; mi < 4; mi++)
                #pragma unroll
                for (int nj = 0; nj < 4; nj++) {
                    mma_f16(acc[mi][nj], ah[mi], bf[nj]);
                    mma_f16(acc[mi][nj], al[mi], bf[nj]);
                }
        }
    }

    // Epilogue
    const int g = lane >> 2;
    #pragma unroll
    for (int mi = 0; mi < 4; mi++) {
        #pragma unroll
        for (int nj = 0; nj < 4; nj++) {
            int row = m0 + wm + mi * 16 + g;
            int col = n0 + wn + nj * 8 + 2 * (lane & 3);
            #pragma unroll
            for (int half = 0; half < 2; half++) {
                int t = row + half * 8;
                float y0 = acc[mi][nj][half * 2 + 0];
                float y1 = acc[mi][nj][half * 2 + 1];
                if (MODE == 0) {
                    *(float2*)&C[(size_t)t * N + col] = make_float2(y0, y1);
                } else { // MODE 3: fused qkv
                    int d = col & 127;
                    if (col < QDIM) {
                        float c0 = ctab[t * HD + d],     s0 = stab[t * HD + d];
                        float c1 = ctab[t * HD + d + 1], s1 = stab[t * HD + d + 1];
                        float r0 = (y0 * c0 - y1 * s0) * ATT_SCALE;
                        float r1 = (y1 * c1 + y0 * s1) * ATT_SCALE;
                        *(__half2*)&QH[(size_t)t * QDIM + col] =
                            __halves2half2(__float2half_rn(r0), __float2half_rn(r1));
                    } else if (col < QDIM + KVDIM) {
                        int kcol = col - QDIM;
                        int hk = kcol >> 7;
                        float c0 = ctab[t * HD + d],     s0 = stab[t * HD + d];
                        float c1 = ctab[t * HD + d + 1], s1 = stab[t * HD + d + 1];
                        float r0 = y0 * c0 - y1 * s0;
                        float r1 = y1 * c1 + y0 * s1;
                        *(__half2*)&KH[(size_t)t * KVDIM + kcol] =
                            __halves2half2(__float2half_rn(r0), __float2half_rn(r1));
                        if (has_out) {
                            #pragma unroll
                            for (int rep = 0; rep < 4; rep++)
                                *(float2*)&outk[(((size_t)(hk * 4 + rep) * L + t) * HD) + d] =
                                    make_float2(r0, r1);
                        }
                    } else {
                        int vcol = col - QDIM - KVDIM;
                        int hk = vcol >> 7;
                        *(__half2*)&VH[(size_t)t * KVDIM + vcol] =
                            __halves2half2(__float2half_rn(y0), __float2half_rn(y1));
                        if (has_out) {
                            #pragma unroll
                            for (int rep = 0; rep < 4; rep++)
                                *(float2*)&outv[(((size_t)(hk * 4 + rep) * L + t) * HD) + d] =
                                    make_float2(y0, y1);
                        }
                    }
                }
            }
        }
    }
}

// ---------------------------------------------------------------------------
// Flash attention on mma.sync fp16, 64-key tiles (R5-proven structure),
// now 2 CTAs/SM (smem 104448B x2 fits 228KB) -> 16 warps/SM.
// ---------------------------------------------------------------------------
#define QS_ST 136
#define KV_ST 136
#define KOFF  (128*QS_ST)            // halves
#define VOFF  (KOFF + 2*64*KV_ST)
#define ATT_SMEM ((KOFF + 4*64*KV_ST) * 2)   // bytes = 104448

__global__ __launch_bounds__(256, 2) void attn_mma(
    const __half* __restrict__ qh, const __half* __restrict__ kh,
    const __half* __restrict__ vh,
    __half* __restrict__ oh, __half* __restrict__ ol)
{
    extern __shared__ char dyn_smem[];
    __half* smh = (__half*)dyn_smem;
    const uint32_t sb = smem_u32(smh);
    const int tid = threadIdx.x, lane = tid & 31, wid = tid >> 5;
    const int h = blockIdx.y, qt = blockIdx.x, kvh = h >> 2;
    const int g = lane >> 2;
    const int lrow = lane & 15, lcol = (lane >> 4) * 8;

    for (int i = tid; i < 2048; i += 256) {
        int r = i >> 4, c = i & 15;
        cp16(smh + r * QS_ST + c * 8,
             qh + (size_t)(qt * 128 + r) * QDIM + h * HD + c * 8);
    }
    CP_COMMIT(); CP_WAIT0();
    __syncthreads();
    uint32_t aQ[8][4];
    #pragma unroll
    for (int ks = 0; ks < 8; ks++)
        ldsm4(aQ[ks], sb + (uint32_t)((wid * 16 + lrow) * QS_ST + ks * 16 + lcol) * 2);
    __syncthreads();

    auto load_kv = [&](int kt) {
        const int s = kt & 1;
        const __half* kg = kh + (size_t)(kt * 64) * KVDIM + kvh * HD;
        const __half* vg = vh + (size_t)(kt * 64) * KVDIM + kvh * HD;
        __half* ksm = smh + KOFF + s * (64 * KV_ST);
        __half* vsm = smh + VOFF + s * (64 * KV_ST);
        for (int i = tid; i < 1024; i += 256) {
            int r = i >> 4, c = i & 15;
            cp16(ksm + r * KV_ST + c * 8, kg + (size_t)r * KVDIM + c * 8);
            cp16(vsm + r * KV_ST + c * 8, vg + (size_t)r * KVDIM + c * 8);
        }
        CP_COMMIT();
    };

    float O[16][4] = {};
    float m0 = -1e30f, m1 = -1e30f, l0 = 0.f, l1 = 0.f;

    load_kv(0);

    for (int kt = 0; kt < 32; kt++) {
        CP_WAIT0();
        __syncthreads();
        if (kt + 1 < 32) load_kv(kt + 1);

        const uint32_t kbase = sb + (uint32_t)(KOFF + (kt & 1) * (64 * KV_ST)) * 2;
        const uint32_t vbase = sb + (uint32_t)(VOFF + (kt & 1) * (64 * KV_ST)) * 2;

        float c[8][4] = {};
        #pragma unroll
        for (int ks = 0; ks < 8; ks++) {
            #pragma unroll
            for (int nh = 0; nh < 4; nh++) {
                uint32_t r[4];
                ldsm4(r, kbase + (uint32_t)((nh * 16 + lrow) * KV_ST + ks * 16 + lcol) * 2);
                uint32_t b0[2] = {r[0], r[2]};
                uint32_t b1[2] = {r[1], r[3]};
                mma_f16(c[nh * 2],     aQ[ks], b0);
                mma_f16(c[nh * 2 + 1], aQ[ks], b1);
            }
        }

        float mx0 = m0, mx1 = m1;
        #pragma unroll
        for (int t = 0; t < 8; t++) {
            mx0 = fmaxf(mx0, fmaxf(c[t][0], c[t][1]));
            mx1 = fmaxf(mx1, fmaxf(c[t][2], c[t][3]));
        }
        mx0 = fmaxf(mx0, __shfl_xor_sync(0xFFFFFFFF, mx0, 1));
        mx0 = fmaxf(mx0, __shfl_xor_sync(0xFFFFFFFF, mx0, 2));
        mx1 = fmaxf(mx1, __shfl_xor_sync(0xFFFFFFFF, mx1, 1));
        mx1 = fmaxf(mx1, __shfl_xor_sync(0xFFFFFFFF, mx1, 2));
        float f0 = __expf(m0 - mx0), f1 = __expf(m1 - mx1);
        m0 = mx0; m1 = mx1;
        float s0 = 0.f, s1 = 0.f;
        #pragma unroll
        for (int t = 0; t < 8; t++) {
            c[t][0] = __expf(c[t][0] - m0); s0 += c[t][0];
            c[t][1] = __expf(c[t][1] - m0); s0 += c[t][1];
            c[t][2] = __expf(c[t][2] - m1); s1 += c[t][2];
            c[t][3] = __expf(c[t][3] - m1); s1 += c[t][3];
        }
        s0 += __shfl_xor_sync(0xFFFFFFFF, s0, 1);
        s0 += __shfl_xor_sync(0xFFFFFFFF, s0, 2);
        s1 += __shfl_xor_sync(0xFFFFFFFF, s1, 1);
        s1 += __shfl_xor_sync(0xFFFFFFFF, s1, 2);
        l0 = l0 * f0 + s0;
        l1 = l1 * f1 + s1;

        #pragma unroll
        for (int t = 0; t < 16; t++) {
            O[t][0] *= f0; O[t][1] *= f0;
            O[t][2] *= f1; O[t][3] *= f1;
        }

        #pragma unroll
        for (int k2 = 0; k2 < 4; k2++) {
            uint32_t a[4];
            a[0] = pack_h2(c[2 * k2][0],     c[2 * k2][1]);
            a[1] = pack_h2(c[2 * k2][2],     c[2 * k2][3]);
            a[2] = pack_h2(c[2 * k2 + 1][0], c[2 * k2 + 1][1]);
            a[3] = pack_h2(c[2 * k2 + 1][2], c[2 * k2 + 1][3]);
            #pragma unroll
            for (int dj = 0; dj < 8; dj++) {
                uint32_t r[4];
                ldsm4t(r, vbase + (uint32_t)((k2 * 16 + lrow) * KV_ST + dj * 16 + lcol) * 2);
                uint32_t b0[2] = {r[0], r[1]};
                uint32_t b1[2] = {r[2], r[3]};
                mma_f16(O[dj * 2],     a, b0);
                mma_f16(O[dj * 2 + 1], a, b1);
            }
        }
        __syncthreads();
    }

    float inv0 = 1.f / l0, inv1 = 1.f / l1;
    const int row0 = qt * 128 + wid * 16 + g;
    #pragma unroll
    for (int t = 0; t < 16; t++) {
        size_t o0 = (size_t)row0 * QDIM + h * HD + t * 8 + 2 * (lane & 3);
        size_t o1 = (size_t)(row0 + 8) * QDIM + h * HD + t * 8 + 2 * (lane & 3);
        float y00 = O[t][0] * inv0, y01 = O[t][1] * inv0;
        float y10 = O[t][2] * inv1, y11 = O[t][3] * inv1;
        __half h00 = __float2half_rn(y00), h01 = __float2half_rn(y01);
        __half h10 = __float2half_rn(y10), h11 = __float2half_rn(y11);
        *(__half2*)(oh + o0) = __halves2half2(h00, h01);
        *(__half2*)(oh + o1) = __halves2half2(h10, h11);
        *(__half2*)(ol + o0) = __halves2half2(
            __float2half_rn(y00 - __half2float(h00)),
            __float2half_rn(y01 - __half2float(h01)));
        *(__half2*)(ol + o1) = __halves2half2(
            __float2half_rn(y10 - __half2float(h10)),
            __float2half_rn(y11 - __half2float(h11)));
    }
}

// ---------------------------------------------------------------------------
// Launch
// ---------------------------------------------------------------------------
extern "C" void kernel_launch(void* const* d_in, const int* in_sizes, int n_in,
                              void* d_out, int out_size)
{
    const float* x  = (const float*)d_in[0];
    const float* wq = (const float*)d_in[1];
    const float* wk = (const float*)d_in[2];
    const float* wv = (const float*)d_in[3];
    const float* wo = (const float*)d_in[4];
    float* out = (float*)d_out;

    __half *pqh, *pkh, *pvh;
    __half *pxh, *pxl, *pah, *pal, *pwT, *pwoT;
    float *pcos, *psin;
    cudaGetSymbolAddress((void**)&pqh,  g_qh);
    cudaGetSymbolAddress((void**)&pkh,  g_kh);
    cudaGetSymbolAddress((void**)&pvh,  g_vh);
    cudaGetSymbolAddress((void**)&pxh,  g_xh);
    cudaGetSymbolAddress((void**)&pxl,  g_xl);
    cudaGetSymbolAddress((void**)&pah,  g_ah);
    cudaGetSymbolAddress((void**)&pal,  g_al);
    cudaGetSymbolAddress((void**)&pwT,  g_wT);
    cudaGetSymbolAddress((void**)&pwoT, g_woT);
    cudaGetSymbolAddress((void**)&pcos, g_cos);
    cudaGetSymbolAddress((void**)&psin, g_sin);

    cudaFuncSetAttribute(gemm_h2<0>, cudaFuncAttributeMaxDynamicSharedMemorySize, GEMM_SMEM);
    cudaFuncSetAttribute(gemm_h2<3>, cudaFuncAttributeMaxDynamicSharedMemorySize, GEMM_SMEM);
    cudaFuncSetAttribute(attn_mma, cudaFuncAttributeMaxDynamicSharedMemorySize, ATT_SMEM);

    // Launch order keeps attn_mma at #5 and gemm_h2<0> at #6 for ncu (-s 5 -c 1).
    rope_tab_kernel<<<(L * HD + 255) / 256, 256>>>(pcos, psin);
    {
        long nx = (long)L * DIM;
        split_h<<<(unsigned)(nx / (256 * 4)), 256>>>(x, pxh, pxl, nx);
    }
    transT_all<<<dim3(320, 128), dim3(32, 8)>>>(wq, wk, wv, wo, pwT, pwoT);

    const long OUT0 = (long)L * QDIM;
    const long KVSZ = (long)NH * L * HD;
    const int has_out = ((long)out_size >= OUT0 + 2 * KVSZ) ? 1 : 0;

    gemm_h2<3><<<dim3(NTOT / 128, L / 128), 256, GEMM_SMEM>>>(
        pxh, pxl, pwT, nullptr, pqh, pkh, pvh, pcos, psin,
        out + OUT0, out + OUT0 + KVSZ, has_out, L, NTOT, DIM);

    attn_mma<<<dim3(L / 128, NH), 256, ATT_SMEM>>>(pqh, pkh, pvh, pah, pal);

    gemm_h2<0><<<dim3(DIM / 128, L / 128), 256, GEMM_SMEM>>>(
        pah, pal, pwoT, out, nullptr, nullptr, nullptr, nullptr, nullptr,
        nullptr, nullptr, 0, L, DIM, DIM);
}

// round 16
// speedup vs baseline: 1.2228x; 1.2228x over previous
#include <cuda_runtime.h>
#include <cuda_fp16.h>
#include <cstdint>
#include <math.h>

// Problem constants
#define L      2048
#define DIM    4096
#define NH     32
#define NKV    8
#define HD     128
#define QDIM   (NH*HD)    // 4096
#define KVDIM  (NKV*HD)   // 1024
#define NTOT   (QDIM + 2*KVDIM)   // 6144 fused projection width
#define ATT_SCALE 0.08838834764831845f  // 128^-0.5

// ---------------------------------------------------------------------------
// Scratch (__device__ globals; no allocations allowed)
// ---------------------------------------------------------------------------
__device__ __half g_qh[L*QDIM];               // q fp16, roped, *ATT_SCALE
__device__ __half g_kh[L*KVDIM];              // k fp16, roped
__device__ __half g_vh[L*KVDIM];              // v fp16
__device__ float  g_cos[L*HD];                // rope cos table [t][j]
__device__ float  g_sin[L*HD];                // rope sin table [t][j]

// fp16 limbs (x: hi+lo; attn out: single fp16; weights: single fp16, transposed)
__device__ __half g_xh[L*DIM],  g_xl[L*DIM];
__device__ __half g_ah[L*QDIM];          // attention output (single limb)
__device__ __half g_wT[NTOT*DIM];        // (wq|wk|wv)^T [N=6144][K=4096]
__device__ __half g_woT[QDIM*DIM];       // wo^T  [N=4096][K=4096]

// ---------------------------------------------------------------------------
// PTX helpers (sm_80-era; valid on base compute_103 target)
// ---------------------------------------------------------------------------
__device__ __forceinline__ uint32_t smem_u32(const void* p) {
    uint32_t a;
    asm("{ .reg .u64 t; cvta.to.shared.u64 t, %1; cvt.u32.u64 %0, t; }" : "=r"(a) : "l"(p));
    return a;
}
__device__ __forceinline__ void cp16(void* smem, const void* g) {
    uint32_t s = smem_u32(smem);
    asm volatile("cp.async.cg.shared.global [%0], [%1], 16;" :: "r"(s), "l"(g));
}
#define CP_COMMIT() asm volatile("cp.async.commit_group;")
#define CP_WAIT0()  asm volatile("cp.async.wait_group 0;")

__device__ __forceinline__ void ldsm4(uint32_t* r, uint32_t addr) {
    asm volatile("ldmatrix.sync.aligned.m8n8.x4.shared.b16 {%0,%1,%2,%3}, [%4];"
                 : "=r"(r[0]), "=r"(r[1]), "=r"(r[2]), "=r"(r[3]) : "r"(addr));
}
__device__ __forceinline__ void ldsm4t(uint32_t* r, uint32_t addr) {
    asm volatile("ldmatrix.sync.aligned.m8n8.x4.trans.shared.b16 {%0,%1,%2,%3}, [%4];"
                 : "=r"(r[0]), "=r"(r[1]), "=r"(r[2]), "=r"(r[3]) : "r"(addr));
}
__device__ __forceinline__ void mma_f16(float* c, const uint32_t* a, const uint32_t* b) {
    asm volatile("mma.sync.aligned.m16n8k16.row.col.f32.f16.f16.f32 "
                 "{%0,%1,%2,%3},{%4,%5,%6,%7},{%8,%9},{%0,%1,%2,%3};"
                 : "+f"(c[0]), "+f"(c[1]), "+f"(c[2]), "+f"(c[3])
                 : "r"(a[0]), "r"(a[1]), "r"(a[2]), "r"(a[3]), "r"(b[0]), "r"(b[1]));
}
__device__ __forceinline__ uint32_t pack_h2(float lo, float hi) {
    uint32_t r;
    asm("cvt.rn.f16x2.f32 %0, %1, %2;" : "=r"(r) : "f"(hi), "f"(lo));
    return r;
}

// ---------------------------------------------------------------------------
// Rope cos/sin table
// ---------------------------------------------------------------------------
__global__ void rope_tab_kernel(float* __restrict__ ct, float* __restrict__ st)
{
    int idx = blockIdx.x * blockDim.x + threadIdx.x;   // t*128 + j
    if (idx >= L * HD) return;
    int t = idx >> 7, j = idx & 127;
    const float Cc = 0.14391156644565413f; // ln(10000)/64
    float a = (float)t * expf(-Cc * (float)(j & 63));
    float c, s;
    sincosf(a, &s, &c);
    ct[idx] = c;
    st[idx] = s;
}

// ---------------------------------------------------------------------------
// fp32 -> fp16 hi + fp16 lo split (x input)
// ---------------------------------------------------------------------------
__global__ void split_h(const float* __restrict__ x,
                        __half* __restrict__ h, __half* __restrict__ l, long n)
{
    long i = ((long)blockIdx.x * blockDim.x + threadIdx.x) * 4;
    if (i >= n) return;
    float4 v = *(const float4*)(x + i);
    float vv[4] = {v.x, v.y, v.z, v.w};
    __half hh[4], ll[4];
    #pragma unroll
    for (int j = 0; j < 4; j++) {
        hh[j] = __float2half_rn(vv[j]);
        ll[j] = __float2half_rn(vv[j] - __half2float(hh[j]));
    }
    *(__half2*)(h + i)     = __halves2half2(hh[0], hh[1]);
    *(__half2*)(h + i + 2) = __halves2half2(hh[2], hh[3]);
    *(__half2*)(l + i)     = __halves2half2(ll[0], ll[1]);
    *(__half2*)(l + i + 2) = __halves2half2(ll[2], ll[3]);
}

// ---------------------------------------------------------------------------
// Merged transpose+convert for all 4 weights.
// ---------------------------------------------------------------------------
__global__ void transT_all(const float* __restrict__ wq, const float* __restrict__ wk,
                           const float* __restrict__ wv, const float* __restrict__ wo,
                           __half* __restrict__ WT, __half* __restrict__ WOT)
{
    __shared__ float t[32][33];
    int bx = blockIdx.x;
    const float* W; __half* H; int N; int n0;
    if (bx < 128)       { W = wq; H = WT;                              N = QDIM;  n0 = bx * 32; }
    else if (bx < 160)  { W = wk; H = WT + (size_t)QDIM * DIM;         N = KVDIM; n0 = (bx - 128) * 32; }
    else if (bx < 192)  { W = wv; H = WT + (size_t)(QDIM + KVDIM) * DIM; N = KVDIM; n0 = (bx - 160) * 32; }
    else                { W = wo; H = WOT;                             N = DIM;   n0 = (bx - 192) * 32; }
    int k0 = blockIdx.y * 32;
    int tx = threadIdx.x, ty = threadIdx.y;
    #pragma unroll
    for (int r = ty; r < 32; r += 8)
        t[r][tx] = W[(size_t)(k0 + r) * N + n0 + tx];
    __syncthreads();
    #pragma unroll
    for (int r = ty; r < 32; r += 8)
        H[(size_t)(n0 + r) * 4096 + k0 + tx] = __float2half_rn(t[tx][r]);
}

// ---------------------------------------------------------------------------
// fp16 GEMM (R13-proven config): C[M,N] = A[M,K] @ B^T[N,K], fp32 acc.
// Block 128x128, BK=64, 256 threads, 8 warps (2M x 4N), warp tile 64x32.
// 2-stage cp.async pipeline, 2 CTAs/SM.
// LIMBS=2: A = Ah + Al (two mma per k16).  LIMBS=1: A = Ah only.
// MODE 0: plain fp32 C.  MODE 3: fused qkv epilogue.
// ---------------------------------------------------------------------------
#define GST    72                 // halves per smem row
#define LIMBB  18432              // bytes per array per stage (128*144)
#define STGB   (3*LIMBB)          // 55296 per stage
#define GEMM_SMEM (2*STGB)        // 110592 -> two CTAs fit

template<int MODE, int LIMBS>
__global__ void __launch_bounds__(256, 2) gemm_h2(
    const __half* __restrict__ Ah, const __half* __restrict__ Al,
    const __half* __restrict__ B,
    float* __restrict__ C,
    __half* __restrict__ QH, __half* __restrict__ KH, __half* __restrict__ VH,
    const float* __restrict__ ctab, const float* __restrict__ stab,
    float* __restrict__ outk, float* __restrict__ outv, int has_out,
    int M, int N, int K)
{
    extern __shared__ char dyn_smem[];
    const uint32_t sb = smem_u32(dyn_smem);
    const int tid = threadIdx.x, lane = tid & 31, wid = tid >> 5;
    const int wm = (wid & 1) * 64, wn = (wid >> 1) * 32;
    const int lrow = lane & 15, lcol = (lane >> 4) * 8;
    const int m0 = blockIdx.y * 128, n0 = blockIdx.x * 128;

    const __half* gAh = Ah + (size_t)m0 * K;
    const __half* gAl = (LIMBS == 2) ? (Al + (size_t)m0 * K) : nullptr;
    const __half* gB  = B  + (size_t)n0 * K;

    float acc[4][4][4] = {};
    const int nit = K / 64;

    auto load_stage = [&](int it) {
        const int s = it & 1;
        const int k0 = it * 64;
        char* base = dyn_smem + s * STGB;
        for (int i = tid; i < 1024; i += 256) {
            int row = i >> 3, c = i & 7;
            uint32_t so = (uint32_t)(row * 144 + c * 16);
            size_t go = (size_t)row * K + k0 + c * 8;
            cp16(base + so, gAh + go);
            if (LIMBS == 2) cp16(base + LIMBB + so, gAl + go);
            cp16(base + 2 * LIMBB + so, gB + go);
        }
        CP_COMMIT();
    };

    load_stage(0);

    for (int it = 0; it < nit; it++) {
        const int s = it & 1;
        CP_WAIT0();
        __syncthreads();
        if (it + 1 < nit) load_stage(it + 1);

        const uint32_t aHb = sb + (uint32_t)(s * STGB);
        const uint32_t aLb = aHb + LIMBB;
        const uint32_t bb  = aHb + 2 * LIMBB;

        #pragma unroll
        for (int ks = 0; ks < 4; ks++) {
            uint32_t ah[4][4], al[4][4], bf[4][2];
            #pragma unroll
            for (int mi = 0; mi < 4; mi++) {
                uint32_t off = (uint32_t)((wm + mi * 16 + lrow) * GST + ks * 16 + lcol) * 2;
                ldsm4(ah[mi], aHb + off);
                if (LIMBS == 2) ldsm4(al[mi], aLb + off);
            }
            #pragma unroll
            for (int nh = 0; nh < 2; nh++) {
                uint32_t off = (uint32_t)((wn + nh * 16 + lrow) * GST + ks * 16 + lcol) * 2;
                uint32_t r[4];
                ldsm4(r, bb + off);
                bf[nh*2][0] = r[0]; bf[nh*2][1] = r[2];
                bf[nh*2+1][0] = r[1]; bf[nh*2+1][1] = r[3];
            }
            #pragma unroll
            for (int mi = 0; mi < 4; mi++)
                #pragma unroll
                for (int nj = 0; nj < 4; nj++) {
                    mma_f16(acc[mi][nj], ah[mi], bf[nj]);
                    if (LIMBS == 2) mma_f16(acc[mi][nj], al[mi], bf[nj]);
                }
        }
    }

    // Epilogue
    const int g = lane >> 2;
    #pragma unroll
    for (int mi = 0; mi < 4; mi++) {
        #pragma unroll
        for (int nj = 0; nj < 4; nj++) {
            int row = m0 + wm + mi * 16 + g;
            int col = n0 + wn + nj * 8 + 2 * (lane & 3);
            #pragma unroll
            for (int half = 0; half < 2; half++) {
                int t = row + half * 8;
                float y0 = acc[mi][nj][half * 2 + 0];
                float y1 = acc[mi][nj][half * 2 + 1];
                if (MODE == 0) {
                    *(float2*)&C[(size_t)t * N + col] = make_float2(y0, y1);
                } else { // MODE 3: fused qkv
                    int d = col & 127;
                    if (col < QDIM) {
                        float c0 = ctab[t * HD + d],     s0 = stab[t * HD + d];
                        float c1 = ctab[t * HD + d + 1], s1 = stab[t * HD + d + 1];
                        float r0 = (y0 * c0 - y1 * s0) * ATT_SCALE;
                        float r1 = (y1 * c1 + y0 * s1) * ATT_SCALE;
                        *(__half2*)&QH[(size_t)t * QDIM + col] =
                            __halves2half2(__float2half_rn(r0), __float2half_rn(r1));
                    } else if (col < QDIM + KVDIM) {
                        int kcol = col - QDIM;
                        int hk = kcol >> 7;
                        float c0 = ctab[t * HD + d],     s0 = stab[t * HD + d];
                        float c1 = ctab[t * HD + d + 1], s1 = stab[t * HD + d + 1];
                        float r0 = y0 * c0 - y1 * s0;
                        float r1 = y1 * c1 + y0 * s1;
                        *(__half2*)&KH[(size_t)t * KVDIM + kcol] =
                            __halves2half2(__float2half_rn(r0), __float2half_rn(r1));
                        if (has_out) {
                            #pragma unroll
                            for (int rep = 0; rep < 4; rep++)
                                *(float2*)&outk[(((size_t)(hk * 4 + rep) * L + t) * HD) + d] =
                                    make_float2(r0, r1);
                        }
                    } else {
                        int vcol = col - QDIM - KVDIM;
                        int hk = vcol >> 7;
                        *(__half2*)&VH[(size_t)t * KVDIM + vcol] =
                            __halves2half2(__float2half_rn(y0), __float2half_rn(y1));
                        if (has_out) {
                            #pragma unroll
                            for (int rep = 0; rep < 4; rep++)
                                *(float2*)&outv[(((size_t)(hk * 4 + rep) * L + t) * HD) + d] =
                                    make_float2(y0, y1);
                        }
                    }
                }
            }
        }
    }
}

// ---------------------------------------------------------------------------
// Flash attention on mma.sync fp16, 128-key tiles, occ-1 (R13-proven).
// Epilogue writes plain fp16 (single limb).
// ---------------------------------------------------------------------------
#define QS_ST 136
#define KV_ST 136
#define KOFF  (128*QS_ST)                 // halves (Q tile)
#define KV_TILE (128*KV_ST)               // halves per 128-key K or V tile
#define VOFF  (KOFF + 2*KV_TILE)
#define ATT_SMEM ((KOFF + 4*KV_TILE) * 2) // bytes = 174080

__global__ __launch_bounds__(256, 1) void attn_mma(
    const __half* __restrict__ qh, const __half* __restrict__ kh,
    const __half* __restrict__ vh, __half* __restrict__ oh)
{
    extern __shared__ char dyn_smem[];
    __half* smh = (__half*)dyn_smem;
    const uint32_t sb = smem_u32(smh);
    const int tid = threadIdx.x, lane = tid & 31, wid = tid >> 5;
    const int h = blockIdx.y, qt = blockIdx.x, kvh = h >> 2;
    const int g = lane >> 2;
    const int lrow = lane & 15, lcol = (lane >> 4) * 8;

    for (int i = tid; i < 2048; i += 256) {
        int r = i >> 4, c = i & 15;
        cp16(smh + r * QS_ST + c * 8,
             qh + (size_t)(qt * 128 + r) * QDIM + h * HD + c * 8);
    }
    CP_COMMIT(); CP_WAIT0();
    __syncthreads();
    uint32_t aQ[8][4];
    #pragma unroll
    for (int ks = 0; ks < 8; ks++)
        ldsm4(aQ[ks], sb + (uint32_t)((wid * 16 + lrow) * QS_ST + ks * 16 + lcol) * 2);
    __syncthreads();

    auto load_kv = [&](int kt) {
        const int s = kt & 1;
        const __half* kg = kh + (size_t)(kt * 128) * KVDIM + kvh * HD;
        const __half* vg = vh + (size_t)(kt * 128) * KVDIM + kvh * HD;
        __half* ksm = smh + KOFF + s * KV_TILE;
        __half* vsm = smh + VOFF + s * KV_TILE;
        for (int i = tid; i < 2048; i += 256) {
            int r = i >> 4, c = i & 15;
            cp16(ksm + r * KV_ST + c * 8, kg + (size_t)r * KVDIM + c * 8);
            cp16(vsm + r * KV_ST + c * 8, vg + (size_t)r * KVDIM + c * 8);
        }
        CP_COMMIT();
    };

    float O[16][4] = {};
    float m0 = -1e30f, m1 = -1e30f, l0 = 0.f, l1 = 0.f;

    load_kv(0);

    for (int kt = 0; kt < 16; kt++) {
        CP_WAIT0();
        __syncthreads();
        if (kt + 1 < 16) load_kv(kt + 1);

        const uint32_t kbase = sb + (uint32_t)(KOFF + (kt & 1) * KV_TILE) * 2;
        const uint32_t vbase = sb + (uint32_t)(VOFF + (kt & 1) * KV_TILE) * 2;

        float c[16][4] = {};
        #pragma unroll
        for (int ks = 0; ks < 8; ks++) {
            #pragma unroll
            for (int nh = 0; nh < 8; nh++) {
                uint32_t r[4];
                ldsm4(r, kbase + (uint32_t)((nh * 16 + lrow) * KV_ST + ks * 16 + lcol) * 2);
                uint32_t b0[2] = {r[0], r[2]};
                uint32_t b1[2] = {r[1], r[3]};
                mma_f16(c[nh * 2],     aQ[ks], b0);
                mma_f16(c[nh * 2 + 1], aQ[ks], b1);
            }
        }

        float mx0 = m0, mx1 = m1;
        #pragma unroll
        for (int t = 0; t < 16; t++) {
            mx0 = fmaxf(mx0, fmaxf(c[t][0], c[t][1]));
            mx1 = fmaxf(mx1, fmaxf(c[t][2], c[t][3]));
        }
        mx0 = fmaxf(mx0, __shfl_xor_sync(0xFFFFFFFF, mx0, 1));
        mx0 = fmaxf(mx0, __shfl_xor_sync(0xFFFFFFFF, mx0, 2));
        mx1 = fmaxf(mx1, __shfl_xor_sync(0xFFFFFFFF, mx1, 1));
        mx1 = fmaxf(mx1, __shfl_xor_sync(0xFFFFFFFF, mx1, 2));
        float f0 = __expf(m0 - mx0), f1 = __expf(m1 - mx1);
        m0 = mx0; m1 = mx1;
        float s0 = 0.f, s1 = 0.f;
        #pragma unroll
        for (int t = 0; t < 16; t++) {
            c[t][0] = __expf(c[t][0] - m0); s0 += c[t][0];
            c[t][1] = __expf(c[t][1] - m0); s0 += c[t][1];
            c[t][2] = __expf(c[t][2] - m1); s1 += c[t][2];
            c[t][3] = __expf(c[t][3] - m1); s1 += c[t][3];
        }
        s0 += __shfl_xor_sync(0xFFFFFFFF, s0, 1);
        s0 += __shfl_xor_sync(0xFFFFFFFF, s0, 2);
        s1 += __shfl_xor_sync(0xFFFFFFFF, s1, 1);
        s1 += __shfl_xor_sync(0xFFFFFFFF, s1, 2);
        l0 = l0 * f0 + s0;
        l1 = l1 * f1 + s1;

        #pragma unroll
        for (int t = 0; t < 16; t++) {
            O[t][0] *= f0; O[t][1] *= f0;
            O[t][2] *= f1; O[t][3] *= f1;
        }

        #pragma unroll
        for (int k2 = 0; k2 < 8; k2++) {
            uint32_t a[4];
            a[0] = pack_h2(c[2 * k2][0],     c[2 * k2][1]);
            a[1] = pack_h2(c[2 * k2][2],     c[2 * k2][3]);
            a[2] = pack_h2(c[2 * k2 + 1][0], c[2 * k2 + 1][1]);
            a[3] = pack_h2(c[2 * k2 + 1][2], c[2 * k2 + 1][3]);
            #pragma unroll
            for (int dj = 0; dj < 8; dj++) {
                uint32_t r[4];
                ldsm4t(r, vbase + (uint32_t)((k2 * 16 + lrow) * KV_ST + dj * 16 + lcol) * 2);
                uint32_t b0[2] = {r[0], r[1]};
                uint32_t b1[2] = {r[2], r[3]};
                mma_f16(O[dj * 2],     a, b0);
                mma_f16(O[dj * 2 + 1], a, b1);
            }
        }
        __syncthreads();
    }

    // Epilogue: normalize and write plain fp16
    float inv0 = 1.f / l0, inv1 = 1.f / l1;
    const int row0 = qt * 128 + wid * 16 + g;
    #pragma unroll
    for (int t = 0; t < 16; t++) {
        size_t o0 = (size_t)row0 * QDIM + h * HD + t * 8 + 2 * (lane & 3);
        size_t o1 = (size_t)(row0 + 8) * QDIM + h * HD + t * 8 + 2 * (lane & 3);
        *(__half2*)(oh + o0) = __floats2half2_rn(O[t][0] * inv0, O[t][1] * inv0);
        *(__half2*)(oh + o1) = __floats2half2_rn(O[t][2] * inv1, O[t][3] * inv1);
    }
}

// ---------------------------------------------------------------------------
// Launch
// ---------------------------------------------------------------------------
extern "C" void kernel_launch(void* const* d_in, const int* in_sizes, int n_in,
                              void* d_out, int out_size)
{
    const float* x  = (const float*)d_in[0];
    const float* wq = (const float*)d_in[1];
    const float* wk = (const float*)d_in[2];
    const float* wv = (const float*)d_in[3];
    const float* wo = (const float*)d_in[4];
    float* out = (float*)d_out;

    __half *pqh, *pkh, *pvh;
    __half *pxh, *pxl, *pah, *pwT, *pwoT;
    float *pcos, *psin;
    cudaGetSymbolAddress((void**)&pqh,  g_qh);
    cudaGetSymbolAddress((void**)&pkh,  g_kh);
    cudaGetSymbolAddress((void**)&pvh,  g_vh);
    cudaGetSymbolAddress((void**)&pxh,  g_xh);
    cudaGetSymbolAddress((void**)&pxl,  g_xl);
    cudaGetSymbolAddress((void**)&pah,  g_ah);
    cudaGetSymbolAddress((void**)&pwT,  g_wT);
    cudaGetSymbolAddress((void**)&pwoT, g_woT);
    cudaGetSymbolAddress((void**)&pcos, g_cos);
    cudaGetSymbolAddress((void**)&psin, g_sin);

    cudaFuncSetAttribute((const void*)gemm_h2<0,1>, cudaFuncAttributeMaxDynamicSharedMemorySize, GEMM_SMEM);
    cudaFuncSetAttribute((const void*)gemm_h2<3,2>, cudaFuncAttributeMaxDynamicSharedMemorySize, GEMM_SMEM);
    cudaFuncSetAttribute(attn_mma, cudaFuncAttributeMaxDynamicSharedMemorySize, ATT_SMEM);

    // Launch order keeps attn at #5 and gemm_h2<0,1> at #6 for ncu (-s 5 -c 1).
    rope_tab_kernel<<<(L * HD + 255) / 256, 256>>>(pcos, psin);
    {
        long nx = (long)L * DIM;
        split_h<<<(unsigned)(nx / (256 * 4)), 256>>>(x, pxh, pxl, nx);
    }
    transT_all<<<dim3(320, 128), dim3(32, 8)>>>(wq, wk, wv, wo, pwT, pwoT);

    const long OUT0 = (long)L * QDIM;
    const long KVSZ = (long)NH * L * HD;
    const int has_out = ((long)out_size >= OUT0 + 2 * KVSZ) ? 1 : 0;

    gemm_h2<3,2><<<dim3(NTOT / 128, L / 128), 256, GEMM_SMEM>>>(
        pxh, pxl, pwT, nullptr, pqh, pkh, pvh, pcos, psin,
        out + OUT0, out + OUT0 + KVSZ, has_out, L, NTOT, DIM);

    attn_mma<<<dim3(L / 128, NH), 256, ATT_SMEM>>>(pqh, pkh, pvh, pah);

    gemm_h2<0,1><<<dim3(DIM / 128, L / 128), 256, GEMM_SMEM>>>(
        pah, nullptr, pwoT, out, nullptr, nullptr, nullptr, nullptr, nullptr,
        nullptr, nullptr, 0, L, DIM, DIM);
}

// round 17
// speedup vs baseline: 1.4051x; 1.1491x over previous
#include <cuda_runtime.h>
#include <cuda_fp16.h>
#include <cstdint>
#include <math.h>

// Problem constants
#define L      2048
#define DIM    4096
#define NH     32
#define NKV    8
#define HD     128
#define QDIM   (NH*HD)    // 4096
#define KVDIM  (NKV*HD)   // 1024
#define NTOT   (QDIM + 2*KVDIM)   // 6144
#define ATT_SCALE 0.08838834764831845f  // 128^-0.5

// ---------------------------------------------------------------------------
// Scratch (__device__ globals; no allocations allowed)
// ---------------------------------------------------------------------------
__device__ __half g_qh[L*QDIM];               // q fp16, roped, *ATT_SCALE
__device__ __half g_kh[L*KVDIM];              // k fp16, roped
__device__ __half g_vh[L*KVDIM];              // v fp16
__device__ float  g_cos[L*HD];                // rope cos table [t][j]
__device__ float  g_sin[L*HD];                // rope sin table [t][j]

// fp16 limbs (x: hi+lo; attn out: single fp16; weights: single fp16, transposed)
__device__ __half g_xh[L*DIM],  g_xl[L*DIM];
__device__ __half g_ah[L*QDIM];          // attention output (single limb)
__device__ __half g_wT[NTOT*DIM];        // (wq|wk|wv)^T [N=6144][K=4096]
__device__ __half g_woT[QDIM*DIM];       // wo^T  [N=4096][K=4096]

// ---------------------------------------------------------------------------
// PTX helpers
// ---------------------------------------------------------------------------
__device__ __forceinline__ uint32_t smem_u32(const void* p) {
    uint32_t a;
    asm("{ .reg .u64 t; cvta.to.shared.u64 t, %1; cvt.u32.u64 %0, t; }" : "=r"(a) : "l"(p));
    return a;
}
__device__ __forceinline__ void cp16(void* smem, const void* g) {
    uint32_t s = smem_u32(smem);
    asm volatile("cp.async.cg.shared.global [%0], [%1], 16;" :: "r"(s), "l"(g));
}
#define CP_COMMIT() asm volatile("cp.async.commit_group;")
#define CP_WAIT0()  asm volatile("cp.async.wait_group 0;")

__device__ __forceinline__ void ldsm4(uint32_t* r, uint32_t addr) {
    asm volatile("ldmatrix.sync.aligned.m8n8.x4.shared.b16 {%0,%1,%2,%3}, [%4];"
                 : "=r"(r[0]), "=r"(r[1]), "=r"(r[2]), "=r"(r[3]) : "r"(addr));
}
__device__ __forceinline__ void ldsm4t(uint32_t* r, uint32_t addr) {
    asm volatile("ldmatrix.sync.aligned.m8n8.x4.trans.shared.b16 {%0,%1,%2,%3}, [%4];"
                 : "=r"(r[0]), "=r"(r[1]), "=r"(r[2]), "=r"(r[3]) : "r"(addr));
}
__device__ __forceinline__ void mma_f16(float* c, const uint32_t* a, const uint32_t* b) {
    asm volatile("mma.sync.aligned.m16n8k16.row.col.f32.f16.f16.f32 "
                 "{%0,%1,%2,%3},{%4,%5,%6,%7},{%8,%9},{%0,%1,%2,%3};"
                 : "+f"(c[0]), "+f"(c[1]), "+f"(c[2]), "+f"(c[3])
                 : "r"(a[0]), "r"(a[1]), "r"(a[2]), "r"(a[3]), "r"(b[0]), "r"(b[1]));
}
__device__ __forceinline__ uint32_t pack_h2(float lo, float hi) {
    uint32_t r;
    asm("cvt.rn.f16x2.f32 %0, %1, %2;" : "=r"(r) : "f"(hi), "f"(lo));
    return r;
}

// ---------------------------------------------------------------------------
// Rope cos/sin table
// ---------------------------------------------------------------------------
__global__ void rope_tab_kernel(float* __restrict__ ct, float* __restrict__ st)
{
    int idx = blockIdx.x * blockDim.x + threadIdx.x;   // t*128 + j
    if (idx >= L * HD) return;
    int t = idx >> 7, j = idx & 127;
    const float Cc = 0.14391156644565413f; // ln(10000)/64
    float a = (float)t * expf(-Cc * (float)(j & 63));
    float c, s;
    sincosf(a, &s, &c);
    ct[idx] = c;
    st[idx] = s;
}

// ---------------------------------------------------------------------------
// fp32 -> fp16 hi + fp16 lo split (x input)
// ---------------------------------------------------------------------------
__global__ void split_h(const float* __restrict__ x,
                        __half* __restrict__ h, __half* __restrict__ l, long n)
{
    long i = ((long)blockIdx.x * blockDim.x + threadIdx.x) * 4;
    if (i >= n) return;
    float4 v = *(const float4*)(x + i);
    float vv[4] = {v.x, v.y, v.z, v.w};
    __half hh[4], ll[4];
    #pragma unroll
    for (int j = 0; j < 4; j++) {
        hh[j] = __float2half_rn(vv[j]);
        ll[j] = __float2half_rn(vv[j] - __half2float(hh[j]));
    }
    *(__half2*)(h + i)     = __halves2half2(hh[0], hh[1]);
    *(__half2*)(h + i + 2) = __halves2half2(hh[2], hh[3]);
    *(__half2*)(l + i)     = __halves2half2(ll[0], ll[1]);
    *(__half2*)(l + i + 2) = __halves2half2(ll[2], ll[3]);
}

// ---------------------------------------------------------------------------
// Merged transpose+convert for all 4 weights.
// ---------------------------------------------------------------------------
__global__ void transT_all(const float* __restrict__ wq, const float* __restrict__ wk,
                           const float* __restrict__ wv, const float* __restrict__ wo,
                           __half* __restrict__ WT, __half* __restrict__ WOT)
{
    __shared__ float t[32][33];
    int bx = blockIdx.x;
    const float* W; __half* H; int N; int n0;
    if (bx < 128)       { W = wq; H = WT;                              N = QDIM;  n0 = bx * 32; }
    else if (bx < 160)  { W = wk; H = WT + (size_t)QDIM * DIM;         N = KVDIM; n0 = (bx - 128) * 32; }
    else if (bx < 192)  { W = wv; H = WT + (size_t)(QDIM + KVDIM) * DIM; N = KVDIM; n0 = (bx - 160) * 32; }
    else                { W = wo; H = WOT;                             N = DIM;   n0 = (bx - 192) * 32; }
    int k0 = blockIdx.y * 32;
    int tx = threadIdx.x, ty = threadIdx.y;
    #pragma unroll
    for (int r = ty; r < 32; r += 8)
        t[r][tx] = W[(size_t)(k0 + r) * N + n0 + tx];
    __syncthreads();
    #pragma unroll
    for (int r = ty; r < 32; r += 8)
        H[(size_t)(n0 + r) * 4096 + k0 + tx] = __float2half_rn(t[tx][r]);
}

// ---------------------------------------------------------------------------
// fp16 GEMM: C[M,N] = A[M,K] @ B^T[N,K], fp32 acc.
// Block 128x128, BK=64, 256 threads, 8 warps (2M x 4N), warp tile 64x32.
// 2-stage cp.async pipeline, 2 CTAs/SM.
// LIMBS=2: A = Ah + Al.  LIMBS=1: A = Ah only.
// MODE 0: plain fp32 C.
// MODE 1: q epilogue (rope + *ATT_SCALE -> QH fp16).
// MODE 2: kv epilogue (col<1024: rope k -> KH + outk; else v -> VH + outv).
// ---------------------------------------------------------------------------
#define GST    72                 // halves per smem row
#define LIMBB  18432              // bytes per array per stage (128*144)
#define STGB   (3*LIMBB)          // 55296 per stage
#define GEMM_SMEM (2*STGB)        // 110592 -> two CTAs fit

template<int MODE, int LIMBS>
__global__ void __launch_bounds__(256, 2) gemm_h2(
    const __half* __restrict__ Ah, const __half* __restrict__ Al,
    const __half* __restrict__ B,
    float* __restrict__ C,
    __half* __restrict__ H1, __half* __restrict__ H2,
    const float* __restrict__ ctab, const float* __restrict__ stab,
    float* __restrict__ outk, float* __restrict__ outv, int has_out,
    int M, int N, int K)
{
    extern __shared__ char dyn_smem[];
    const uint32_t sb = smem_u32(dyn_smem);
    const int tid = threadIdx.x, lane = tid & 31, wid = tid >> 5;
    const int wm = (wid & 1) * 64, wn = (wid >> 1) * 32;
    const int lrow = lane & 15, lcol = (lane >> 4) * 8;
    const int m0 = blockIdx.y * 128, n0 = blockIdx.x * 128;

    const __half* gAh = Ah + (size_t)m0 * K;
    const __half* gAl = (LIMBS == 2) ? (Al + (size_t)m0 * K) : nullptr;
    const __half* gB  = B  + (size_t)n0 * K;

    float acc[4][4][4] = {};
    const int nit = K / 64;

    auto load_stage = [&](int it) {
        const int s = it & 1;
        const int k0 = it * 64;
        char* base = dyn_smem + s * STGB;
        for (int i = tid; i < 1024; i += 256) {
            int row = i >> 3, c = i & 7;
            uint32_t so = (uint32_t)(row * 144 + c * 16);
            size_t go = (size_t)row * K + k0 + c * 8;
            cp16(base + so, gAh + go);
            if (LIMBS == 2) cp16(base + LIMBB + so, gAl + go);
            cp16(base + 2 * LIMBB + so, gB + go);
        }
        CP_COMMIT();
    };

    load_stage(0);

    for (int it = 0; it < nit; it++) {
        const int s = it & 1;
        CP_WAIT0();
        __syncthreads();
        if (it + 1 < nit) load_stage(it + 1);

        const uint32_t aHb = sb + (uint32_t)(s * STGB);
        const uint32_t aLb = aHb + LIMBB;
        const uint32_t bb  = aHb + 2 * LIMBB;

        #pragma unroll
        for (int ks = 0; ks < 4; ks++) {
            uint32_t ah[4][4], al[4][4], bf[4][2];
            #pragma unroll
            for (int mi = 0; mi < 4; mi++) {
                uint32_t off = (uint32_t)((wm + mi * 16 + lrow) * GST + ks * 16 + lcol) * 2;
                ldsm4(ah[mi], aHb + off);
                if (LIMBS == 2) ldsm4(al[mi], aLb + off);
            }
            #pragma unroll
            for (int nh = 0; nh < 2; nh++) {
                uint32_t off = (uint32_t)((wn + nh * 16 + lrow) * GST + ks * 16 + lcol) * 2;
                uint32_t r[4];
                ldsm4(r, bb + off);
                bf[nh*2][0] = r[0]; bf[nh*2][1] = r[2];
                bf[nh*2+1][0] = r[1]; bf[nh*2+1][1] = r[3];
            }
            #pragma unroll
            for (int mi = 0; mi < 4; mi++)
                #pragma unroll
                for (int nj = 0; nj < 4; nj++) {
                    mma_f16(acc[mi][nj], ah[mi], bf[nj]);
                    if (LIMBS == 2) mma_f16(acc[mi][nj], al[mi], bf[nj]);
                }
        }
    }

    // Epilogue
    const int g = lane >> 2;
    #pragma unroll
    for (int mi = 0; mi < 4; mi++) {
        #pragma unroll
        for (int nj = 0; nj < 4; nj++) {
            int row = m0 + wm + mi * 16 + g;
            int col = n0 + wn + nj * 8 + 2 * (lane & 3);
            #pragma unroll
            for (int half = 0; half < 2; half++) {
                int t = row + half * 8;
                float y0 = acc[mi][nj][half * 2 + 0];
                float y1 = acc[mi][nj][half * 2 + 1];
                if (MODE == 0) {
                    *(float2*)&C[(size_t)t * N + col] = make_float2(y0, y1);
                } else if (MODE == 1) {     // q: rope + scale -> H1
                    int d = col & 127;
                    float c0 = ctab[t * HD + d],     s0 = stab[t * HD + d];
                    float c1 = ctab[t * HD + d + 1], s1 = stab[t * HD + d + 1];
                    float r0 = (y0 * c0 - y1 * s0) * ATT_SCALE;
                    float r1 = (y1 * c1 + y0 * s1) * ATT_SCALE;
                    *(__half2*)&H1[(size_t)t * QDIM + col] =
                        __halves2half2(__float2half_rn(r0), __float2half_rn(r1));
                } else {                    // MODE 2: kv
                    int d = col & 127;
                    if (col < KVDIM) {      // k: rope -> H1 + outk
                        int hk = col >> 7;
                        float c0 = ctab[t * HD + d],     s0 = stab[t * HD + d];
                        float c1 = ctab[t * HD + d + 1], s1 = stab[t * HD + d + 1];
                        float r0 = y0 * c0 - y1 * s0;
                        float r1 = y1 * c1 + y0 * s1;
                        *(__half2*)&H1[(size_t)t * KVDIM + col] =
                            __halves2half2(__float2half_rn(r0), __float2half_rn(r1));
                        if (has_out) {
                            #pragma unroll
                            for (int rep = 0; rep < 4; rep++)
                                *(float2*)&outk[(((size_t)(hk * 4 + rep) * L + t) * HD) + d] =
                                    make_float2(r0, r1);
                        }
                    } else {                // v -> H2 + outv
                        int vcol = col - KVDIM;
                        int hk = vcol >> 7;
                        *(__half2*)&H2[(size_t)t * KVDIM + vcol] =
                            __halves2half2(__float2half_rn(y0), __float2half_rn(y1));
                        if (has_out) {
                            #pragma unroll
                            for (int rep = 0; rep < 4; rep++)
                                *(float2*)&outv[(((size_t)(hk * 4 + rep) * L + t) * HD) + d] =
                                    make_float2(y0, y1);
                        }
                    }
                }
            }
        }
    }
}

// ---------------------------------------------------------------------------
// Flash attention on mma.sync fp16, 128-key tiles, occ-1 (R13/R16-proven).
// Epilogue writes plain fp16 (single limb).
// ---------------------------------------------------------------------------
#define QS_ST 136
#define KV_ST 136
#define KOFF  (128*QS_ST)                 // halves (Q tile)
#define KV_TILE (128*KV_ST)               // halves per 128-key K or V tile
#define VOFF  (KOFF + 2*KV_TILE)
#define ATT_SMEM ((KOFF + 4*KV_TILE) * 2) // bytes = 174080

__global__ __launch_bounds__(256, 1) void attn_mma(
    const __half* __restrict__ qh, const __half* __restrict__ kh,
    const __half* __restrict__ vh, __half* __restrict__ oh)
{
    extern __shared__ char dyn_smem[];
    __half* smh = (__half*)dyn_smem;
    const uint32_t sb = smem_u32(smh);
    const int tid = threadIdx.x, lane = tid & 31, wid = tid >> 5;
    const int h = blockIdx.y, qt = blockIdx.x, kvh = h >> 2;
    const int g = lane >> 2;
    const int lrow = lane & 15, lcol = (lane >> 4) * 8;

    for (int i = tid; i < 2048; i += 256) {
        int r = i >> 4, c = i & 15;
        cp16(smh + r * QS_ST + c * 8,
             qh + (size_t)(qt * 128 + r) * QDIM + h * HD + c * 8);
    }
    CP_COMMIT(); CP_WAIT0();
    __syncthreads();
    uint32_t aQ[8][4];
    #pragma unroll
    for (int ks = 0; ks < 8; ks++)
        ldsm4(aQ[ks], sb + (uint32_t)((wid * 16 + lrow) * QS_ST + ks * 16 + lcol) * 2);
    __syncthreads();

    auto load_kv = [&](int kt) {
        const int s = kt & 1;
        const __half* kg = kh + (size_t)(kt * 128) * KVDIM + kvh * HD;
        const __half* vg = vh + (size_t)(kt * 128) * KVDIM + kvh * HD;
        __half* ksm = smh + KOFF + s * KV_TILE;
        __half* vsm = smh + VOFF + s * KV_TILE;
        for (int i = tid; i < 2048; i += 256) {
            int r = i >> 4, c = i & 15;
            cp16(ksm + r * KV_ST + c * 8, kg + (size_t)r * KVDIM + c * 8);
            cp16(vsm + r * KV_ST + c * 8, vg + (size_t)r * KVDIM + c * 8);
        }
        CP_COMMIT();
    };

    float O[16][4] = {};
    float m0 = -1e30f, m1 = -1e30f, l0 = 0.f, l1 = 0.f;

    load_kv(0);

    for (int kt = 0; kt < 16; kt++) {
        CP_WAIT0();
        __syncthreads();
        if (kt + 1 < 16) load_kv(kt + 1);

        const uint32_t kbase = sb + (uint32_t)(KOFF + (kt & 1) * KV_TILE) * 2;
        const uint32_t vbase = sb + (uint32_t)(VOFF + (kt & 1) * KV_TILE) * 2;

        float c[16][4] = {};
        #pragma unroll
        for (int ks = 0; ks < 8; ks++) {
            #pragma unroll
            for (int nh = 0; nh < 8; nh++) {
                uint32_t r[4];
                ldsm4(r, kbase + (uint32_t)((nh * 16 + lrow) * KV_ST + ks * 16 + lcol) * 2);
                uint32_t b0[2] = {r[0], r[2]};
                uint32_t b1[2] = {r[1], r[3]};
                mma_f16(c[nh * 2],     aQ[ks], b0);
                mma_f16(c[nh * 2 + 1], aQ[ks], b1);
            }
        }

        float mx0 = m0, mx1 = m1;
        #pragma unroll
        for (int t = 0; t < 16; t++) {
            mx0 = fmaxf(mx0, fmaxf(c[t][0], c[t][1]));
            mx1 = fmaxf(mx1, fmaxf(c[t][2], c[t][3]));
        }
        mx0 = fmaxf(mx0, __shfl_xor_sync(0xFFFFFFFF, mx0, 1));
        mx0 = fmaxf(mx0, __shfl_xor_sync(0xFFFFFFFF, mx0, 2));
        mx1 = fmaxf(mx1, __shfl_xor_sync(0xFFFFFFFF, mx1, 1));
        mx1 = fmaxf(mx1, __shfl_xor_sync(0xFFFFFFFF, mx1, 2));
        float f0 = __expf(m0 - mx0), f1 = __expf(m1 - mx1);
        m0 = mx0; m1 = mx1;
        float s0 = 0.f, s1 = 0.f;
        #pragma unroll
        for (int t = 0; t < 16; t++) {
            c[t][0] = __expf(c[t][0] - m0); s0 += c[t][0];
            c[t][1] = __expf(c[t][1] - m0); s0 += c[t][1];
            c[t][2] = __expf(c[t][2] - m1); s1 += c[t][2];
            c[t][3] = __expf(c[t][3] - m1); s1 += c[t][3];
        }
        s0 += __shfl_xor_sync(0xFFFFFFFF, s0, 1);
        s0 += __shfl_xor_sync(0xFFFFFFFF, s0, 2);
        s1 += __shfl_xor_sync(0xFFFFFFFF, s1, 1);
        s1 += __shfl_xor_sync(0xFFFFFFFF, s1, 2);
        l0 = l0 * f0 + s0;
        l1 = l1 * f1 + s1;

        #pragma unroll
        for (int t = 0; t < 16; t++) {
            O[t][0] *= f0; O[t][1] *= f0;
            O[t][2] *= f1; O[t][3] *= f1;
        }

        #pragma unroll
        for (int k2 = 0; k2 < 8; k2++) {
            uint32_t a[4];
            a[0] = pack_h2(c[2 * k2][0],     c[2 * k2][1]);
            a[1] = pack_h2(c[2 * k2][2],     c[2 * k2][3]);
            a[2] = pack_h2(c[2 * k2 + 1][0], c[2 * k2 + 1][1]);
            a[3] = pack_h2(c[2 * k2 + 1][2], c[2 * k2 + 1][3]);
            #pragma unroll
            for (int dj = 0; dj < 8; dj++) {
                uint32_t r[4];
                ldsm4t(r, vbase + (uint32_t)((k2 * 16 + lrow) * KV_ST + dj * 16 + lcol) * 2);
                uint32_t b0[2] = {r[0], r[1]};
                uint32_t b1[2] = {r[2], r[3]};
                mma_f16(O[dj * 2],     a, b0);
                mma_f16(O[dj * 2 + 1], a, b1);
            }
        }
        __syncthreads();
    }

    // Epilogue: normalize and write plain fp16
    float inv0 = 1.f / l0, inv1 = 1.f / l1;
    const int row0 = qt * 128 + wid * 16 + g;
    #pragma unroll
    for (int t = 0; t < 16; t++) {
        size_t o0 = (size_t)row0 * QDIM + h * HD + t * 8 + 2 * (lane & 3);
        size_t o1 = (size_t)(row0 + 8) * QDIM + h * HD + t * 8 + 2 * (lane & 3);
        *(__half2*)(oh + o0) = __floats2half2_rn(O[t][0] * inv0, O[t][1] * inv0);
        *(__half2*)(oh + o1) = __floats2half2_rn(O[t][2] * inv1, O[t][3] * inv1);
    }
}

// ---------------------------------------------------------------------------
// Launch
// ---------------------------------------------------------------------------
extern "C" void kernel_launch(void* const* d_in, const int* in_sizes, int n_in,
                              void* d_out, int out_size)
{
    const float* x  = (const float*)d_in[0];
    const float* wq = (const float*)d_in[1];
    const float* wk = (const float*)d_in[2];
    const float* wv = (const float*)d_in[3];
    const float* wo = (const float*)d_in[4];
    float* out = (float*)d_out;

    __half *pqh, *pkh, *pvh;
    __half *pxh, *pxl, *pah, *pwT, *pwoT;
    float *pcos, *psin;
    cudaGetSymbolAddress((void**)&pqh,  g_qh);
    cudaGetSymbolAddress((void**)&pkh,  g_kh);
    cudaGetSymbolAddress((void**)&pvh,  g_vh);
    cudaGetSymbolAddress((void**)&pxh,  g_xh);
    cudaGetSymbolAddress((void**)&pxl,  g_xl);
    cudaGetSymbolAddress((void**)&pah,  g_ah);
    cudaGetSymbolAddress((void**)&pwT,  g_wT);
    cudaGetSymbolAddress((void**)&pwoT, g_woT);
    cudaGetSymbolAddress((void**)&pcos, g_cos);
    cudaGetSymbolAddress((void**)&psin, g_sin);

    cudaFuncSetAttribute((const void*)gemm_h2<0,1>, cudaFuncAttributeMaxDynamicSharedMemorySize, GEMM_SMEM);
    cudaFuncSetAttribute((const void*)gemm_h2<1,1>, cudaFuncAttributeMaxDynamicSharedMemorySize, GEMM_SMEM);
    cudaFuncSetAttribute((const void*)gemm_h2<2,2>, cudaFuncAttributeMaxDynamicSharedMemorySize, GEMM_SMEM);
    cudaFuncSetAttribute(attn_mma, cudaFuncAttributeMaxDynamicSharedMemorySize, ATT_SMEM);

    // Launch order: (1) rope_tab (2) split (3) transT (4) gemm_q (5) gemm_kv
    //               (6) attn  <- ncu capture target   (7) gemm_wo
    rope_tab_kernel<<<(L * HD + 255) / 256, 256>>>(pcos, psin);
    {
        long nx = (long)L * DIM;
        split_h<<<(unsigned)(nx / (256 * 4)), 256>>>(x, pxh, pxl, nx);
    }
    transT_all<<<dim3(320, 128), dim3(32, 8)>>>(wq, wk, wv, wo, pwT, pwoT);

    const long OUT0 = (long)L * QDIM;
    const long KVSZ = (long)NH * L * HD;
    const int has_out = ((long)out_size >= OUT0 + 2 * KVSZ) ? 1 : 0;

    // q projection: single limb (q is consumed at fp16 precision anyway)
    gemm_h2<1,1><<<dim3(QDIM / 128, L / 128), 256, GEMM_SMEM>>>(
        pxh, nullptr, pwT, nullptr, pqh, nullptr, pcos, psin,
        nullptr, nullptr, 0, L, QDIM, DIM);

    // kv projection: two limbs (k/v are direct fp32 outputs)
    gemm_h2<2,2><<<dim3(2 * KVDIM / 128, L / 128), 256, GEMM_SMEM>>>(
        pxh, pxl, pwT + (size_t)QDIM * DIM, nullptr, pkh, pvh, pcos, psin,
        out + OUT0, out + OUT0 + KVSZ, has_out, L, 2 * KVDIM, DIM);

    // flash attention
    attn_mma<<<dim3(L / 128, NH), 256, ATT_SMEM>>>(pqh, pkh, pvh, pah);

    // output projection: single limb
    gemm_h2<0,1><<<dim3(DIM / 128, L / 128), 256, GEMM_SMEM>>>(
        pah, nullptr, pwoT, out, nullptr, nullptr, nullptr, nullptr,
        nullptr, nullptr, 0, L, DIM, DIM);
}